// round 2
// baseline (speedup 1.0000x reference)
#include <cuda_runtime.h>
#include <math.h>

#define B_  2048
#define D_  64
#define H_  512
#define BT  8      // samples per block
#define NT  128    // threads per block

// Precomputed E[j][k] = W2[j,k] * sum_{m<64} W1[m,j] * W3[k,m]
__device__ float g_E[H_ * H_];

// ---------------------------------------------------------------------------
// Kernel 0: build E (input-independent bilinear kernel of the divergence).
// grid = H_ (j), block = H_ (k). 16.8M MACs total — negligible.
// ---------------------------------------------------------------------------
__global__ __launch_bounds__(H_) void compute_E_kernel(
    const float* __restrict__ W1,   // (65, 512)
    const float* __restrict__ W2,   // (512, 512)
    const float* __restrict__ W3)   // (512, 64)
{
    __shared__ float w1col[D_];
    const int j = blockIdx.x;
    const int k = threadIdx.x;
    if (k < D_) w1col[k] = W1[k * H_ + j];   // W1[m, j], m < 64
    __syncthreads();

    // load W3 row k into registers (contiguous per thread)
    float r[D_];
    const float4* w3r = (const float4*)(W3 + k * D_);
#pragma unroll
    for (int q = 0; q < D_ / 4; q++) {
        float4 v = w3r[q];
        r[4*q+0] = v.x; r[4*q+1] = v.y; r[4*q+2] = v.z; r[4*q+3] = v.w;
    }
    float acc = 0.f;
#pragma unroll
    for (int m = 0; m < D_; m++) acc = fmaf(w1col[m], r[m], acc);

    g_E[j * H_ + k] = W2[j * H_ + k] * acc;
}

// ---------------------------------------------------------------------------
// Main kernel: 8 samples per block, 128 threads.
//  Phase 1: h1 = tanh([x,t] @ W1 + b1)                (thread owns 4 j, 8 s)
//  Phase 2: z2 = h1 @ W2 ; a = (1-h1^2) @ E  (fused)  (thread owns 4 k, 8 s)
//           h2 = tanh(z2+b2); div += a * (1-h2^2)
//  Phase 3: out = (h2 @ W3 + b3)/2 ; out[:,64] = div/2
// ---------------------------------------------------------------------------
__global__ __launch_bounds__(NT) void cnf_main_kernel(
    const float* __restrict__ t,  const float* __restrict__ x,
    const float* __restrict__ W1, const float* __restrict__ b1,
    const float* __restrict__ W2, const float* __restrict__ b2,
    const float* __restrict__ W3, const float* __restrict__ b3,
    float* __restrict__ out)
{
    __shared__ float sh_h0[BT][D_ + 1];   // [s][i]  (i=64 is t)
    __shared__ float sh_h1[H_][BT];       // [j][s]
    __shared__ float sh_h2[H_][BT];       // [k][s]
    __shared__ float sh_wdiv[4][BT];      // per-warp divergence partials

    const int tid = threadIdx.x;
    const int s0  = blockIdx.x * BT;

    // load x tile (+t)
    for (int idx = tid; idx < BT * (D_ + 1); idx += NT) {
        int s = idx / (D_ + 1);
        int i = idx - s * (D_ + 1);
        sh_h0[s][i] = (i < D_) ? x[(size_t)(s0 + s) * (D_ + 1) + i] : t[0];
    }
    __syncthreads();

    // ---- Phase 1: layer 1 -------------------------------------------------
    {
        const int j0 = tid * 4;
        float acc[BT][4];
#pragma unroll
        for (int s = 0; s < BT; s++)
#pragma unroll
            for (int q = 0; q < 4; q++) acc[s][q] = 0.f;

        for (int i = 0; i < D_ + 1; i++) {
            float4 w = *(const float4*)(W1 + i * H_ + j0);
            float wv[4] = {w.x, w.y, w.z, w.w};
#pragma unroll
            for (int s = 0; s < BT; s++) {
                float h = sh_h0[s][i];
#pragma unroll
                for (int q = 0; q < 4; q++) acc[s][q] = fmaf(h, wv[q], acc[s][q]);
            }
        }
        float4 bb = *(const float4*)(b1 + j0);
        float bv[4] = {bb.x, bb.y, bb.z, bb.w};
#pragma unroll
        for (int q = 0; q < 4; q++)
#pragma unroll
            for (int s = 0; s < BT; s++)
                sh_h1[j0 + q][s] = tanhf(acc[s][q] + bv[q]);
    }
    __syncthreads();

    // ---- Phase 2: layer 2 + fused divergence bilinear ----------------------
    const int k0 = tid * 4;
    float z[BT][4], a[BT][4];
#pragma unroll
    for (int s = 0; s < BT; s++)
#pragma unroll
        for (int q = 0; q < 4; q++) { z[s][q] = 0.f; a[s][q] = 0.f; }

#pragma unroll 2
    for (int j = 0; j < H_; j++) {
        float4 w   = *(const float4*)(W2  + j * H_ + k0);
        float4 e   = *(const float4*)(g_E + j * H_ + k0);
        float4 hlo = *(const float4*)(&sh_h1[j][0]);
        float4 hhi = *(const float4*)(&sh_h1[j][4]);
        float hv[BT] = {hlo.x, hlo.y, hlo.z, hlo.w, hhi.x, hhi.y, hhi.z, hhi.w};
        float wv[4]  = {w.x, w.y, w.z, w.w};
        float ev[4]  = {e.x, e.y, e.z, e.w};
#pragma unroll
        for (int s = 0; s < BT; s++) {
            float u = fmaf(-hv[s], hv[s], 1.f);   // 1 - h1^2
#pragma unroll
            for (int q = 0; q < 4; q++) {
                z[s][q] = fmaf(hv[s], wv[q], z[s][q]);
                a[s][q] = fmaf(u,     ev[q], a[s][q]);
            }
        }
    }

    float divp[BT];
    {
        float4 bb = *(const float4*)(b2 + k0);
        float bv[4] = {bb.x, bb.y, bb.z, bb.w};
#pragma unroll
        for (int s = 0; s < BT; s++) divp[s] = 0.f;
#pragma unroll
        for (int s = 0; s < BT; s++)
#pragma unroll
            for (int q = 0; q < 4; q++) {
                float h2 = tanhf(z[s][q] + bv[q]);
                float v  = fmaf(-h2, h2, 1.f);    // 1 - h2^2
                divp[s]  = fmaf(a[s][q], v, divp[s]);
                sh_h2[k0 + q][s] = h2;
            }
    }
    // warp-reduce the divergence partials (each lane holds 4 k's worth)
#pragma unroll
    for (int s = 0; s < BT; s++) {
#pragma unroll
        for (int off = 16; off > 0; off >>= 1)
            divp[s] += __shfl_xor_sync(0xffffffffu, divp[s], off);
    }
    if ((tid & 31) == 0) {
        int w = tid >> 5;
#pragma unroll
        for (int s = 0; s < BT; s++) sh_wdiv[w][s] = divp[s];
    }
    __syncthreads();

    // ---- Phase 3: layer 3 + writeback --------------------------------------
    {
        const int s  = tid >> 4;          // 0..7
        const int m0 = (tid & 15) * 4;    // 0..60
        float4 bb3 = *(const float4*)(b3 + m0);
        float o[4] = {bb3.x, bb3.y, bb3.z, bb3.w};
#pragma unroll 4
        for (int k = 0; k < H_; k++) {
            float  hv = sh_h2[k][s];
            float4 w  = *(const float4*)(W3 + k * D_ + m0);
            o[0] = fmaf(hv, w.x, o[0]);
            o[1] = fmaf(hv, w.y, o[1]);
            o[2] = fmaf(hv, w.z, o[2]);
            o[3] = fmaf(hv, w.w, o[3]);
        }
        // rows are 65 floats -> not 16B aligned, scalar stores
        float* op = out + (size_t)(s0 + s) * (D_ + 1) + m0;
        op[0] = 0.5f * o[0];
        op[1] = 0.5f * o[1];
        op[2] = 0.5f * o[2];
        op[3] = 0.5f * o[3];
    }
    if (tid < BT) {
        float d = sh_wdiv[0][tid] + sh_wdiv[1][tid] +
                  sh_wdiv[2][tid] + sh_wdiv[3][tid];
        out[(size_t)(s0 + tid) * (D_ + 1) + D_] = 0.5f * d;
    }
}

extern "C" void kernel_launch(void* const* d_in, const int* in_sizes, int n_in,
                              void* d_out, int out_size) {
    const float* t  = (const float*)d_in[0];
    const float* x  = (const float*)d_in[1];
    const float* W1 = (const float*)d_in[2];
    const float* b1 = (const float*)d_in[3];
    const float* W2 = (const float*)d_in[4];
    const float* b2 = (const float*)d_in[5];
    const float* W3 = (const float*)d_in[6];
    const float* b3 = (const float*)d_in[7];
    float* out = (float*)d_out;

    compute_E_kernel<<<H_, H_>>>(W1, W2, W3);
    cnf_main_kernel<<<B_ / BT, NT>>>(t, x, W1, b1, W2, b2, W3, b3, out);
}